// round 9
// baseline (speedup 1.0000x reference)
#include <cuda_runtime.h>
#include <cuda_bf16.h>
#include <math.h>
#include <cstdint>

// ---------------------------------------------------------------------------
// NnBoard768 NNUE eval — round 9.
// Toolchain fact learned R8: harness compiles via compute_103 (no 'a'
// features) -> tcgen05/TMEM unusable. Optimize the SMEM-gather kernel:
//   * 148 CTAs (4 chunks x 37 row-groups), uneven row split -> all SMs busy
//   * packed fma.rn.f32x2 (base sm_100+ ISA): 4 FFMA2 instead of 8 FFMA/piece
//   * bf16 unpack writes directly into 64-bit pair halves
// Weights bf16 in SMEM (192KB chunk), fp32 accumulation, fused epilogue +
// last-CTA sigmoid reduction. rel_err class unchanged (~1.3e-4).
// ---------------------------------------------------------------------------

#define BATCH   8192
#define PIECES  32
#define NNZ     (BATCH * PIECES)
#define NFEAT   768
#define FTOUT   512
#define CHUNK   128
#define NCHUNK  (FTOUT / CHUNK)     // 4
#define NGROUPS 37
#define NCTA    (NCHUNK * NGROUPS)  // 148
#define THREADS 1024
#define WARPS   (THREADS / 32)      // 32

#define SMEM_W_ELEMS (NFEAT * CHUNK)                          // 98304 bf16 = 192KB
#define SMEM_BYTES   (SMEM_W_ELEMS * 2 + WARPS * PIECES * 16) // 208KB

__device__ float        g_partial[NCHUNK][BATCH];
__device__ unsigned int g_done = 0;

// unpack u32 holding 2 bf16 (lo, hi) into a packed f32x2 register pair
__device__ __forceinline__ unsigned long long bfpair(uint32_t u) {
    unsigned long long r;
    asm("{ .reg .b32 lo, hi;\n\t"
        "shl.b32 lo, %1, 16;\n\t"
        "and.b32 hi, %1, 0xFFFF0000;\n\t"
        "mov.b64 %0, {lo, hi}; }" : "=l"(r) : "r"(u));
    return r;
}
#define FMA2(acc, a, b) \
    asm("fma.rn.f32x2 %0, %1, %2, %0;" : "+l"(acc) : "l"(a), "l"(b))

__global__ __launch_bounds__(THREADS, 1)
void ft_partial_kernel(const int*   __restrict__ stm_idx,    // [2, NNZ] (int32 or int64 words)
                       const int*   __restrict__ nstm_idx,   // [2, NNZ]
                       const float* __restrict__ values,     // [NNZ]
                       const float* __restrict__ ft_w,       // [768, 512]
                       const float* __restrict__ ft_b,       // [512]
                       const float* __restrict__ out_w,      // [1024, 1]
                       const float* __restrict__ out_b,      // [1]
                       float*       __restrict__ out)        // [8192, 1]
{
    extern __shared__ __align__(16) char smem_raw[];
    __nv_bfloat16* wb    = (__nv_bfloat16*)smem_raw;               // [768][128]
    int4*          stage = (int4*)(smem_raw + SMEM_W_ELEMS * 2);   // [WARPS][32]
    __shared__ unsigned int is_last;

    const int chunk = blockIdx.x;
    const int cbase = chunk * CHUNK;
    const int tid   = threadIdx.x;
    const int warp  = tid >> 5;
    const int lane  = tid & 31;

    // Index dtype detection from the deterministic batch-id row:
    // int32 layout: word[32] = batch id of nnz 32 = 1 ; int64 layout: word[32]
    // = low half of int64 element 16 (batch id 0) = 0.
    const bool is64 = (stm_idx[32] == 0);

    // --- Stage the 768x128 weight chunk into SMEM as bf16 ---
    for (int i = tid; i < SMEM_W_ELEMS / 4; i += THREADS) {
        int f  = i >> 5;        // 32 float4-groups per 128-col row
        int c4 = i & 31;
        float4 v = *(const float4*)(ft_w + f * FTOUT + cbase + c4 * 4);
        __nv_bfloat162 lo = __floats2bfloat162_rn(v.x, v.y);
        __nv_bfloat162 hi = __floats2bfloat162_rn(v.z, v.w);
        uint2 packed;
        packed.x = *(unsigned int*)&lo;
        packed.y = *(unsigned int*)&hi;
        *(uint2*)(wb + f * CHUNK + c4 * 4) = packed;   // 8B, conflict-free
    }

    // --- Per-lane epilogue constants: lane owns cols [col0, col0+4) ---
    const int col0 = cbase + 4 * lane;
    float ows[4], own[4], fb[4];
    #pragma unroll
    for (int j = 0; j < 4; ++j) {
        ows[j] = out_w[col0 + j];
        own[j] = out_w[FTOUT + col0 + j];
        fb[j]  = ft_b[col0 + j];
    }

    __syncthreads();

    int4* mystage = stage + warp * PIECES;
    const char* wbase = (const char*)wb + 8 * lane;    // 4 bf16 = 8 bytes/lane

    // Uneven row split across 37 groups: all 148 SMs get ~222 rows.
    const int g        = blockIdx.y;
    const int rowstart = (BATCH * g) / NGROUPS;
    const int rowend   = (BATCH * (g + 1)) / NGROUPS;

    for (int row = rowstart + warp; row < rowend; row += WARPS) {
        const int off = row * PIECES + lane;   // one nnz per lane, coalesced

        int sf, nf;
        if (is64) {
            sf = stm_idx[2 * NNZ + 2 * off];   // low word of int64 feature id
            nf = nstm_idx[2 * NNZ + 2 * off];
        } else {
            sf = stm_idx[NNZ + off];
            nf = nstm_idx[NNZ + off];
        }
        sf = min(max(sf, 0), NFEAT - 1);       // never trap on any input bytes
        nf = min(max(nf, 0), NFEAT - 1);
        const float v = values[off];

        // stage pre-scaled byte offsets (256B per bf16x128 feature row)
        mystage[lane] = make_int4(sf * (CHUNK * 2), nf * (CHUNK * 2),
                                  __float_as_int(v), 0);
        __syncwarp();

        unsigned long long A01 = 0ull, A23 = 0ull, B01 = 0ull, B23 = 0ull;
        #pragma unroll
        for (int p = 0; p < PIECES; ++p) {
            const int4 pr = mystage[p];                        // LDS.128 bcast
            unsigned long long vv2;
            asm("mov.b64 %0, {%1, %1};" : "=l"(vv2) : "r"(pr.z));
            const uint2 sraw = *(const uint2*)(wbase + pr.x);  // LDS.64
            const uint2 nraw = *(const uint2*)(wbase + pr.y);  // LDS.64
            FMA2(A01, vv2, bfpair(sraw.x));
            FMA2(A23, vv2, bfpair(sraw.y));
            FMA2(B01, vv2, bfpair(nraw.x));
            FMA2(B23, vv2, bfpair(nraw.y));
        }
        __syncwarp();   // all lanes done reading stage before next overwrite

        float a0, a1, a2, a3, b0, b1, b2, b3;
        asm("mov.b64 {%0, %1}, %2;" : "=f"(a0), "=f"(a1) : "l"(A01));
        asm("mov.b64 {%0, %1}, %2;" : "=f"(a2), "=f"(a3) : "l"(A23));
        asm("mov.b64 {%0, %1}, %2;" : "=f"(b0), "=f"(b1) : "l"(B01));
        asm("mov.b64 {%0, %1}, %2;" : "=f"(b2), "=f"(b3) : "l"(B23));

        // bias + clip[0,1] + fold in the out_w GEMV for this chunk
        a0 = fminf(fmaxf(a0 + fb[0], 0.f), 1.f);
        a1 = fminf(fmaxf(a1 + fb[1], 0.f), 1.f);
        a2 = fminf(fmaxf(a2 + fb[2], 0.f), 1.f);
        a3 = fminf(fmaxf(a3 + fb[3], 0.f), 1.f);
        b0 = fminf(fmaxf(b0 + fb[0], 0.f), 1.f);
        b1 = fminf(fmaxf(b1 + fb[1], 0.f), 1.f);
        b2 = fminf(fmaxf(b2 + fb[2], 0.f), 1.f);
        b3 = fminf(fmaxf(b3 + fb[3], 0.f), 1.f);

        float part = a0 * ows[0] + a1 * ows[1] + a2 * ows[2] + a3 * ows[3]
                   + b0 * own[0] + b1 * own[1] + b2 * own[2] + b3 * own[3];
        #pragma unroll
        for (int d = 16; d > 0; d >>= 1)
            part += __shfl_xor_sync(0xffffffffu, part, d);

        if (lane == 0)
            g_partial[chunk][row] = part;
    }

    // --- Fused final reduction: last CTA to finish does the sigmoid pass ---
    __syncthreads();
    if (tid == 0) {
        __threadfence();
        unsigned int t = atomicAdd(&g_done, 1);
        is_last = (t == NCTA - 1) ? 1u : 0u;
    }
    __syncthreads();
    if (is_last) {
        if (tid == 0) g_done = 0;              // reset for next graph replay
        const float ob = out_b[0];
        for (int b = tid; b < BATCH; b += THREADS) {
            float x = ob + g_partial[0][b] + g_partial[1][b]
                         + g_partial[2][b] + g_partial[3][b];
            out[b] = 1.0f / (1.0f + __expf(-x));
        }
    }
}

// Opt in to >48KB dynamic smem ONCE, before main() — never during capture.
namespace {
struct _FtInit {
    _FtInit() {
        cudaError_t e = cudaFuncSetAttribute(
            ft_partial_kernel,
            cudaFuncAttributeMaxDynamicSharedMemorySize, SMEM_BYTES);
        if (e != cudaSuccess) {
            (void)cudaGetLastError();
            (void)cudaFuncSetAttribute(
                ft_partial_kernel,
                cudaFuncAttributeMaxDynamicSharedMemorySize, SMEM_BYTES);
        }
    }
} _ft_init;
}

extern "C" void kernel_launch(void* const* d_in, const int* in_sizes, int n_in,
                              void* d_out, int out_size)
{
    const int*   stm    = (const int*)  d_in[0];
    const int*   nstm   = (const int*)  d_in[1];
    const float* values = (const float*)d_in[2];
    const float* ft_w   = (const float*)d_in[3];
    const float* ft_b   = (const float*)d_in[4];
    const float* out_w  = (const float*)d_in[5];
    const float* out_b  = (const float*)d_in[6];
    float*       out    = (float*)d_out;

    ft_partial_kernel<<<dim3(NCHUNK, NGROUPS), THREADS, SMEM_BYTES>>>(
        stm, nstm, values, ft_w, ft_b, out_w, out_b, out);
}

// round 10
// speedup vs baseline: 1.0305x; 1.0305x over previous
#include <cuda_runtime.h>
#include <cuda_bf16.h>
#include <math.h>
#include <cstdint>

// ---------------------------------------------------------------------------
// NnBoard768 NNUE eval — round 10.
// R9 lesson: packed fma.rn.f32x2 inline-asm caused register spills (L2 2->43%,
// issue 65->39%) -> reverted to the proven R5 scalar-FFMA loop. Kept the one
// clean change: 148 CTAs (4 chunks x 37 row groups) so every SM is busy.
//   * 768x128 bf16 weight chunk resident in SMEM (192KB)
//   * staged per-warp piece triples, LDS.128 broadcast + 2x LDS.64 gathers
//   * fp32 accumulation, fused bias+clip+out_w dot, last-CTA sigmoid
// ---------------------------------------------------------------------------

#define BATCH   8192
#define PIECES  32
#define NNZ     (BATCH * PIECES)
#define NFEAT   768
#define FTOUT   512
#define CHUNK   128
#define NCHUNK  (FTOUT / CHUNK)     // 4
#define NGROUPS 37
#define NCTA    (NCHUNK * NGROUPS)  // 148
#define THREADS 1024
#define WARPS   (THREADS / 32)      // 32

#define SMEM_W_ELEMS (NFEAT * CHUNK)                          // 98304 bf16 = 192KB
#define SMEM_BYTES   (SMEM_W_ELEMS * 2 + WARPS * PIECES * 16) // 208KB

__device__ float        g_partial[NCHUNK][BATCH];
__device__ unsigned int g_done = 0;

// bf16 (lo/hi half of a packed u32) -> f32 by bit surgery: single ALU op each.
__device__ __forceinline__ float bflo(unsigned int u) { return __int_as_float((int)(u << 16)); }
__device__ __forceinline__ float bfhi(unsigned int u) { return __int_as_float((int)(u & 0xffff0000u)); }

__global__ __launch_bounds__(THREADS, 1)
void ft_partial_kernel(const int*   __restrict__ stm_idx,    // [2, NNZ] (int32 or int64 words)
                       const int*   __restrict__ nstm_idx,   // [2, NNZ]
                       const float* __restrict__ values,     // [NNZ]
                       const float* __restrict__ ft_w,       // [768, 512]
                       const float* __restrict__ ft_b,       // [512]
                       const float* __restrict__ out_w,      // [1024, 1]
                       const float* __restrict__ out_b,      // [1]
                       float*       __restrict__ out)        // [8192, 1]
{
    extern __shared__ __align__(16) char smem_raw[];
    __nv_bfloat16* wb    = (__nv_bfloat16*)smem_raw;               // [768][128]
    int4*          stage = (int4*)(smem_raw + SMEM_W_ELEMS * 2);   // [WARPS][32]
    __shared__ unsigned int is_last;

    const int chunk = blockIdx.x;
    const int cbase = chunk * CHUNK;
    const int tid   = threadIdx.x;
    const int warp  = tid >> 5;
    const int lane  = tid & 31;

    // Index dtype detection from the deterministic batch-id row:
    // int32 layout: word[32] = batch id of nnz 32 = 1 ; int64 layout: word[32]
    // = low half of int64 element 16 (batch id 0) = 0.
    const bool is64 = (stm_idx[32] == 0);

    // --- Stage the 768x128 weight chunk into SMEM as bf16 ---
    for (int i = tid; i < SMEM_W_ELEMS / 4; i += THREADS) {
        int f  = i >> 5;        // 32 float4-groups per 128-col row
        int c4 = i & 31;
        float4 v = *(const float4*)(ft_w + f * FTOUT + cbase + c4 * 4);
        __nv_bfloat162 lo = __floats2bfloat162_rn(v.x, v.y);
        __nv_bfloat162 hi = __floats2bfloat162_rn(v.z, v.w);
        uint2 packed;
        packed.x = *(unsigned int*)&lo;
        packed.y = *(unsigned int*)&hi;
        *(uint2*)(wb + f * CHUNK + c4 * 4) = packed;   // 8B, conflict-free
    }

    // --- Per-lane epilogue constants: lane owns cols [col0, col0+4) ---
    const int col0 = cbase + 4 * lane;
    float ows[4], own[4], fb[4];
    #pragma unroll
    for (int j = 0; j < 4; ++j) {
        ows[j] = out_w[col0 + j];
        own[j] = out_w[FTOUT + col0 + j];
        fb[j]  = ft_b[col0 + j];
    }

    __syncthreads();

    int4* mystage = stage + warp * PIECES;
    const char* wbase = (const char*)wb + 8 * lane;    // 4 bf16 = 8 bytes/lane

    // Uneven row split across 37 groups: all 148 SMs busy, <=222 rows each.
    const int g        = blockIdx.y;
    const int rowstart = (BATCH * g) / NGROUPS;
    const int rowend   = (BATCH * (g + 1)) / NGROUPS;

    for (int row = rowstart + warp; row < rowend; row += WARPS) {
        const int off = row * PIECES + lane;   // one nnz per lane, coalesced

        int sf, nf;
        if (is64) {
            sf = stm_idx[2 * NNZ + 2 * off];   // low word of int64 feature id
            nf = nstm_idx[2 * NNZ + 2 * off];
        } else {
            sf = stm_idx[NNZ + off];
            nf = nstm_idx[NNZ + off];
        }
        sf = min(max(sf, 0), NFEAT - 1);       // never trap on any input bytes
        nf = min(max(nf, 0), NFEAT - 1);
        const float v = values[off];

        // stage pre-scaled byte offsets (256B per bf16x128 feature row)
        mystage[lane] = make_int4(sf * (CHUNK * 2), nf * (CHUNK * 2),
                                  __float_as_int(v), 0);
        __syncwarp();

        float a0 = 0.f, a1 = 0.f, a2 = 0.f, a3 = 0.f;
        float b0 = 0.f, b1 = 0.f, b2 = 0.f, b3 = 0.f;
        #pragma unroll
        for (int p = 0; p < PIECES; ++p) {
            const int4 pr = mystage[p];                        // LDS.128 bcast
            const float vv = __int_as_float(pr.z);
            const uint2 sraw = *(const uint2*)(wbase + pr.x);  // LDS.64
            const uint2 nraw = *(const uint2*)(wbase + pr.y);  // LDS.64
            a0 = fmaf(vv, bflo(sraw.x), a0);
            a1 = fmaf(vv, bfhi(sraw.x), a1);
            a2 = fmaf(vv, bflo(sraw.y), a2);
            a3 = fmaf(vv, bfhi(sraw.y), a3);
            b0 = fmaf(vv, bflo(nraw.x), b0);
            b1 = fmaf(vv, bfhi(nraw.x), b1);
            b2 = fmaf(vv, bflo(nraw.y), b2);
            b3 = fmaf(vv, bfhi(nraw.y), b3);
        }
        __syncwarp();   // all lanes done reading stage before next overwrite

        // bias + clip[0,1] + fold in the out_w GEMV for this chunk
        a0 = fminf(fmaxf(a0 + fb[0], 0.f), 1.f);
        a1 = fminf(fmaxf(a1 + fb[1], 0.f), 1.f);
        a2 = fminf(fmaxf(a2 + fb[2], 0.f), 1.f);
        a3 = fminf(fmaxf(a3 + fb[3], 0.f), 1.f);
        b0 = fminf(fmaxf(b0 + fb[0], 0.f), 1.f);
        b1 = fminf(fmaxf(b1 + fb[1], 0.f), 1.f);
        b2 = fminf(fmaxf(b2 + fb[2], 0.f), 1.f);
        b3 = fminf(fmaxf(b3 + fb[3], 0.f), 1.f);

        float part = a0 * ows[0] + a1 * ows[1] + a2 * ows[2] + a3 * ows[3]
                   + b0 * own[0] + b1 * own[1] + b2 * own[2] + b3 * own[3];
        #pragma unroll
        for (int d = 16; d > 0; d >>= 1)
            part += __shfl_xor_sync(0xffffffffu, part, d);

        if (lane == 0)
            g_partial[chunk][row] = part;
    }

    // --- Fused final reduction: last CTA to finish does the sigmoid pass ---
    __syncthreads();
    if (tid == 0) {
        __threadfence();
        unsigned int t = atomicAdd(&g_done, 1);
        is_last = (t == NCTA - 1) ? 1u : 0u;
    }
    __syncthreads();
    if (is_last) {
        if (tid == 0) g_done = 0;              // reset for next graph replay
        const float ob = out_b[0];
        for (int b = tid; b < BATCH; b += THREADS) {
            float x = ob + g_partial[0][b] + g_partial[1][b]
                         + g_partial[2][b] + g_partial[3][b];
            out[b] = 1.0f / (1.0f + __expf(-x));
        }
    }
}

// Opt in to >48KB dynamic smem ONCE, before main() — never during capture.
namespace {
struct _FtInit {
    _FtInit() {
        cudaError_t e = cudaFuncSetAttribute(
            ft_partial_kernel,
            cudaFuncAttributeMaxDynamicSharedMemorySize, SMEM_BYTES);
        if (e != cudaSuccess) {
            (void)cudaGetLastError();
            (void)cudaFuncSetAttribute(
                ft_partial_kernel,
                cudaFuncAttributeMaxDynamicSharedMemorySize, SMEM_BYTES);
        }
    }
} _ft_init;
}

extern "C" void kernel_launch(void* const* d_in, const int* in_sizes, int n_in,
                              void* d_out, int out_size)
{
    const int*   stm    = (const int*)  d_in[0];
    const int*   nstm   = (const int*)  d_in[1];
    const float* values = (const float*)d_in[2];
    const float* ft_w   = (const float*)d_in[3];
    const float* ft_b   = (const float*)d_in[4];
    const float* out_w  = (const float*)d_in[5];
    const float* out_b  = (const float*)d_in[6];
    float*       out    = (float*)d_out;

    ft_partial_kernel<<<dim3(NCHUNK, NGROUPS), THREADS, SMEM_BYTES>>>(
        stm, nstm, values, ft_w, ft_b, out_w, out_b, out);
}

// round 11
// speedup vs baseline: 1.7273x; 1.6761x over previous
#include <cuda_runtime.h>
#include <cuda_bf16.h>
#include <math.h>
#include <cstdint>

// ---------------------------------------------------------------------------
// NnBoard768 NNUE eval — round 11.
// R10 lesson: the 43.7us kernel's speed comes from the STATIC outer row loop
// (ptxas unrolls it and front-batches the index LDGs; dynamic bounds exposed
// per-row LDG latency -> L2 40%, issue 47%, 66us). This round keeps the
// static trip count AND fills all 148 SMs: 37 groups x 224 fixed rows
// (7 per warp, compile-time), overhang handled by clamped loads + predicated
// stores (96 phantom rows ~ 1% waste).
//   * 768x128 bf16 weight chunk resident in SMEM (192KB)
//   * staged piece triples, LDS.128 broadcast + 2x LDS.64 gathers, fp32 acc
//   * fused bias+clip+out_w dot, last-CTA sigmoid reduction
// ---------------------------------------------------------------------------

#define BATCH   8192
#define PIECES  32
#define NNZ     (BATCH * PIECES)
#define NFEAT   768
#define FTOUT   512
#define CHUNK   128
#define NCHUNK  (FTOUT / CHUNK)     // 4
#define NGROUPS 37
#define NCTA    (NCHUNK * NGROUPS)  // 148
#define THREADS 1024
#define WARPS   (THREADS / 32)      // 32
#define ROWS_PER_CTA  224           // fixed; 37*224 = 8288 >= 8192
#define ROWS_PER_WARP 7             // compile-time trip count (the key!)

#define SMEM_W_ELEMS (NFEAT * CHUNK)                          // 98304 bf16 = 192KB
#define SMEM_BYTES   (SMEM_W_ELEMS * 2 + WARPS * PIECES * 16) // 208KB

__device__ float        g_partial[NCHUNK][BATCH];
__device__ unsigned int g_done = 0;

// bf16 (lo/hi half of a packed u32) -> f32 by bit surgery: single ALU op each.
__device__ __forceinline__ float bflo(unsigned int u) { return __int_as_float((int)(u << 16)); }
__device__ __forceinline__ float bfhi(unsigned int u) { return __int_as_float((int)(u & 0xffff0000u)); }

__global__ __launch_bounds__(THREADS, 1)
void ft_partial_kernel(const int*   __restrict__ stm_idx,    // [2, NNZ] (int32 or int64 words)
                       const int*   __restrict__ nstm_idx,   // [2, NNZ]
                       const float* __restrict__ values,     // [NNZ]
                       const float* __restrict__ ft_w,       // [768, 512]
                       const float* __restrict__ ft_b,       // [512]
                       const float* __restrict__ out_w,      // [1024, 1]
                       const float* __restrict__ out_b,      // [1]
                       float*       __restrict__ out)        // [8192, 1]
{
    extern __shared__ __align__(16) char smem_raw[];
    __nv_bfloat16* wb    = (__nv_bfloat16*)smem_raw;               // [768][128]
    int4*          stage = (int4*)(smem_raw + SMEM_W_ELEMS * 2);   // [WARPS][32]
    __shared__ unsigned int is_last;

    const int chunk = blockIdx.x;
    const int cbase = chunk * CHUNK;
    const int tid   = threadIdx.x;
    const int warp  = tid >> 5;
    const int lane  = tid & 31;

    // Index dtype detection from the deterministic batch-id row:
    // int32 layout: word[32] = batch id of nnz 32 = 1 ; int64 layout: word[32]
    // = low half of int64 element 16 (batch id 0) = 0.
    const bool is64 = (stm_idx[32] == 0);

    // --- Stage the 768x128 weight chunk into SMEM as bf16 ---
    for (int i = tid; i < SMEM_W_ELEMS / 4; i += THREADS) {
        int f  = i >> 5;        // 32 float4-groups per 128-col row
        int c4 = i & 31;
        float4 v = *(const float4*)(ft_w + f * FTOUT + cbase + c4 * 4);
        __nv_bfloat162 lo = __floats2bfloat162_rn(v.x, v.y);
        __nv_bfloat162 hi = __floats2bfloat162_rn(v.z, v.w);
        uint2 packed;
        packed.x = *(unsigned int*)&lo;
        packed.y = *(unsigned int*)&hi;
        *(uint2*)(wb + f * CHUNK + c4 * 4) = packed;   // 8B, conflict-free
    }

    // --- Per-lane epilogue constants: lane owns cols [col0, col0+4) ---
    const int col0 = cbase + 4 * lane;
    float ows[4], own[4], fb[4];
    #pragma unroll
    for (int j = 0; j < 4; ++j) {
        ows[j] = out_w[col0 + j];
        own[j] = out_w[FTOUT + col0 + j];
        fb[j]  = ft_b[col0 + j];
    }

    __syncthreads();

    int4* mystage = stage + warp * PIECES;
    const char* wbase = (const char*)wb + 8 * lane;    // 4 bf16 = 8 bytes/lane
    const int rowbase = blockIdx.y * ROWS_PER_CTA + warp;

    #pragma unroll
    for (int r = 0; r < ROWS_PER_WARP; ++r) {
        const int row  = rowbase + r * WARPS;
        const int rowc = min(row, BATCH - 1);      // clamp: loads always valid
        const int off  = rowc * PIECES + lane;     // one nnz per lane, coalesced

        int sf, nf;
        if (is64) {
            sf = stm_idx[2 * NNZ + 2 * off];       // low word of int64 feature id
            nf = nstm_idx[2 * NNZ + 2 * off];
        } else {
            sf = stm_idx[NNZ + off];
            nf = nstm_idx[NNZ + off];
        }
        sf = min(max(sf, 0), NFEAT - 1);           // never trap on any input bytes
        nf = min(max(nf, 0), NFEAT - 1);
        const float v = values[off];

        // stage pre-scaled byte offsets (256B per bf16x128 feature row)
        mystage[lane] = make_int4(sf * (CHUNK * 2), nf * (CHUNK * 2),
                                  __float_as_int(v), 0);
        __syncwarp();

        float a0 = 0.f, a1 = 0.f, a2 = 0.f, a3 = 0.f;
        float b0 = 0.f, b1 = 0.f, b2 = 0.f, b3 = 0.f;
        #pragma unroll
        for (int p = 0; p < PIECES; ++p) {
            const int4 pr = mystage[p];                        // LDS.128 bcast
            const float vv = __int_as_float(pr.z);
            const uint2 sraw = *(const uint2*)(wbase + pr.x);  // LDS.64
            const uint2 nraw = *(const uint2*)(wbase + pr.y);  // LDS.64
            a0 = fmaf(vv, bflo(sraw.x), a0);
            a1 = fmaf(vv, bfhi(sraw.x), a1);
            a2 = fmaf(vv, bflo(sraw.y), a2);
            a3 = fmaf(vv, bfhi(sraw.y), a3);
            b0 = fmaf(vv, bflo(nraw.x), b0);
            b1 = fmaf(vv, bfhi(nraw.x), b1);
            b2 = fmaf(vv, bflo(nraw.y), b2);
            b3 = fmaf(vv, bfhi(nraw.y), b3);
        }
        __syncwarp();   // all lanes done reading stage before next overwrite

        // bias + clip[0,1] + fold in the out_w GEMV for this chunk
        a0 = fminf(fmaxf(a0 + fb[0], 0.f), 1.f);
        a1 = fminf(fmaxf(a1 + fb[1], 0.f), 1.f);
        a2 = fminf(fmaxf(a2 + fb[2], 0.f), 1.f);
        a3 = fminf(fmaxf(a3 + fb[3], 0.f), 1.f);
        b0 = fminf(fmaxf(b0 + fb[0], 0.f), 1.f);
        b1 = fminf(fmaxf(b1 + fb[1], 0.f), 1.f);
        b2 = fminf(fmaxf(b2 + fb[2], 0.f), 1.f);
        b3 = fminf(fmaxf(b3 + fb[3], 0.f), 1.f);

        float part = a0 * ows[0] + a1 * ows[1] + a2 * ows[2] + a3 * ows[3]
                   + b0 * own[0] + b1 * own[1] + b2 * own[2] + b3 * own[3];
        #pragma unroll
        for (int d = 16; d > 0; d >>= 1)
            part += __shfl_xor_sync(0xffffffffu, part, d);

        if (lane == 0 && row < BATCH)          // store predicated, loads weren't
            g_partial[chunk][row] = part;
    }

    // --- Fused final reduction: last CTA to finish does the sigmoid pass ---
    __syncthreads();
    if (tid == 0) {
        __threadfence();
        unsigned int t = atomicAdd(&g_done, 1);
        is_last = (t == NCTA - 1) ? 1u : 0u;
    }
    __syncthreads();
    if (is_last) {
        if (tid == 0) g_done = 0;              // reset for next graph replay
        const float ob = out_b[0];
        for (int b = tid; b < BATCH; b += THREADS) {
            float x = ob + g_partial[0][b] + g_partial[1][b]
                         + g_partial[2][b] + g_partial[3][b];
            out[b] = 1.0f / (1.0f + __expf(-x));
        }
    }
}

// Opt in to >48KB dynamic smem ONCE, before main() — never during capture.
namespace {
struct _FtInit {
    _FtInit() {
        cudaError_t e = cudaFuncSetAttribute(
            ft_partial_kernel,
            cudaFuncAttributeMaxDynamicSharedMemorySize, SMEM_BYTES);
        if (e != cudaSuccess) {
            (void)cudaGetLastError();
            (void)cudaFuncSetAttribute(
                ft_partial_kernel,
                cudaFuncAttributeMaxDynamicSharedMemorySize, SMEM_BYTES);
        }
    }
} _ft_init;
}

extern "C" void kernel_launch(void* const* d_in, const int* in_sizes, int n_in,
                              void* d_out, int out_size)
{
    const int*   stm    = (const int*)  d_in[0];
    const int*   nstm   = (const int*)  d_in[1];
    const float* values = (const float*)d_in[2];
    const float* ft_w   = (const float*)d_in[3];
    const float* ft_b   = (const float*)d_in[4];
    const float* out_w  = (const float*)d_in[5];
    const float* out_b  = (const float*)d_in[6];
    float*       out    = (float*)d_out;

    ft_partial_kernel<<<dim3(NCHUNK, NGROUPS), THREADS, SMEM_BYTES>>>(
        stm, nstm, values, ft_w, ft_b, out_w, out_b, out);
}